// round 3
// baseline (speedup 1.0000x reference)
#include <cuda_runtime.h>

// ---------------- problem constants ----------------
#define MAXN 50000
#define MAXE 1600000
#define HID 128
#define HEADS 4
#define NGRAPH 64

// ---------------- scratch (static device memory; no allocations) ----------------
__device__ __align__(256) float g_xlxr[(size_t)MAXN * 256]; // [N,256]: 0..127 = xl, 128..255 = xr
__device__ __align__(256) float g_h1[(size_t)MAXN * HID];
__device__ __align__(256) float g_h2[(size_t)MAXN * HID];
__device__ __align__(256) float g_w[((size_t)MAXE + MAXN) * HEADS];
__device__ __align__(256) float g_denom[(size_t)MAXN * HEADS];
__device__ __align__(256) int   g_src[MAXE + MAXN];
__device__ __align__(256) int   g_dst[MAXE + MAXN];
__device__ __align__(256) int   g_batch[MAXN];
__device__ float g_pool[NGRAPH * HID];
__device__ float g_cnt[NGRAPH];
__device__ int   g_is64;

// ---------------- dtype detect: int64 indices have zero high words ----------------
__global__ void detect_kernel(const unsigned* __restrict__ p)
{
    if (threadIdx.x == 0) {
        unsigned o = 0;
        for (int i = 0; i < 256; i++) o |= p[2 * i + 1];
        g_is64 = (o == 0) ? 1 : 0;
    }
}

__device__ __forceinline__ int load_idx(const void* p, int i, int is64, int N)
{
    long long v = is64 ? ((const long long*)p)[i] : (long long)((const int*)p)[i];
    int r = (int)v;
    return r < 0 ? 0 : (r >= N ? N - 1 : r);
}

// canonicalize edges (+appended self-loops) and batch to int32
__global__ void convert_kernel(const void* __restrict__ ei, const void* __restrict__ batch,
                               int E, int N)
{
    int is64 = g_is64;
    int ET = E + N;
    for (int i = blockIdx.x * blockDim.x + threadIdx.x; i < ET;
         i += gridDim.x * blockDim.x) {
        if (i < E) {
            g_src[i] = load_idx(ei, i, is64, N);
            g_dst[i] = load_idx(ei, E + i, is64, N);
        } else {
            g_src[i] = i - E;
            g_dst[i] = i - E;
        }
        if (i < N) g_batch[i] = load_idx(batch, i, is64, NGRAPH);
    }
}

// ---------------- fused GEMM: C[:,0:128] = A @ Wl^T + bl ; C[:,128:256] = A @ Wr^T + br ----
__global__ void gemm_nt(const float* __restrict__ A,
                        const float* __restrict__ Wl, const float* __restrict__ Wr,
                        const float* __restrict__ bl, const float* __restrict__ br,
                        float* __restrict__ C, int M, int K)
{
    __shared__ float As[8][128];
    __shared__ float Ws[8][128];
    const float* W  = blockIdx.y ? Wr : Wl;
    const float* bv = blockIdx.y ? br : bl;

    int m0 = blockIdx.x * 128;
    int t = threadIdx.x;               // 256 threads
    int tx = t & 15;
    int ty = t >> 4;
    int lrow = t >> 1;                 // 0..127
    int lseg = (t & 1) * 4;            // 0 or 4

    float acc[8][8];
#pragma unroll
    for (int i = 0; i < 8; i++)
#pragma unroll
        for (int j = 0; j < 8; j++) acc[i][j] = 0.f;

    for (int k0 = 0; k0 < K; k0 += 8) {
        int ar = m0 + lrow;
        int arc = ar < M ? ar : M - 1;
        float4 av = *(const float4*)(A + (size_t)arc * K + k0 + lseg);
        As[lseg + 0][lrow] = av.x; As[lseg + 1][lrow] = av.y;
        As[lseg + 2][lrow] = av.z; As[lseg + 3][lrow] = av.w;
        float4 wv = *(const float4*)(W + (size_t)lrow * K + k0 + lseg);
        Ws[lseg + 0][lrow] = wv.x; Ws[lseg + 1][lrow] = wv.y;
        Ws[lseg + 2][lrow] = wv.z; Ws[lseg + 3][lrow] = wv.w;
        __syncthreads();
#pragma unroll
        for (int kk = 0; kk < 8; kk++) {
            float4 a0 = *(const float4*)&As[kk][ty * 8];
            float4 a1 = *(const float4*)&As[kk][ty * 8 + 4];
            float4 w0 = *(const float4*)&Ws[kk][tx * 8];
            float4 w1 = *(const float4*)&Ws[kk][tx * 8 + 4];
            float ra[8] = {a0.x, a0.y, a0.z, a0.w, a1.x, a1.y, a1.z, a1.w};
            float rw[8] = {w0.x, w0.y, w0.z, w0.w, w1.x, w1.y, w1.z, w1.w};
#pragma unroll
            for (int i = 0; i < 8; i++)
#pragma unroll
                for (int j = 0; j < 8; j++) acc[i][j] += ra[i] * rw[j];
        }
        __syncthreads();
    }

    float bias[8];
#pragma unroll
    for (int j = 0; j < 8; j++) bias[j] = bv[tx * 8 + j];

#pragma unroll
    for (int i = 0; i < 8; i++) {
        int row = m0 + ty * 8 + i;
        if (row < M) {
            float* dst = C + (size_t)row * 256 + blockIdx.y * 128 + tx * 8;
            *(float4*)(dst + 0) = make_float4(acc[i][0] + bias[0], acc[i][1] + bias[1],
                                              acc[i][2] + bias[2], acc[i][3] + bias[3]);
            *(float4*)(dst + 4) = make_float4(acc[i][4] + bias[4], acc[i][5] + bias[5],
                                              acc[i][6] + bias[6], acc[i][7] + bias[7]);
        }
    }
}

// ---------------- edge pass 1: alpha -> exp -> denom ----------------
__device__ __forceinline__ float lrelu(float x) {
    return fmaxf(x, 0.f) + 0.2f * fminf(x, 0.f);
}

__global__ void edge_alpha(int ET, const float* __restrict__ att)
{
    int w = (int)((blockIdx.x * (unsigned)blockDim.x + threadIdx.x) >> 5);
    int lane = threadIdx.x & 31;
    if (w >= ET) return;
    int src = g_src[w];
    int dst = g_dst[w];

    float4 xl4 = *(const float4*)(&g_xlxr[(size_t)src * 256 + 4 * lane]);
    float4 xr4 = *(const float4*)(&g_xlxr[(size_t)dst * 256 + 128 + 4 * lane]);
    float4 a4 = ((const float4*)att)[lane];

    float p = lrelu(xl4.x + xr4.x) * a4.x
            + lrelu(xl4.y + xr4.y) * a4.y
            + lrelu(xl4.z + xr4.z) * a4.z
            + lrelu(xl4.w + xr4.w) * a4.w;
    p += __shfl_xor_sync(0xFFFFFFFFu, p, 1);
    p += __shfl_xor_sync(0xFFFFFFFFu, p, 2);
    p += __shfl_xor_sync(0xFFFFFFFFu, p, 4);

    float wexp = __expf(p);
    if ((lane & 7) == 0) {
        int h = lane >> 3;
        g_w[(size_t)w * HEADS + h] = wexp;
        atomicAdd(&g_denom[(size_t)dst * HEADS + h], wexp);
    }
}

// ---------------- edge pass 2: out[dst] += xl[src] * (w/denom[dst]) ----------------
__global__ void edge_agg(int ET, float* __restrict__ out)
{
    int w = (int)((blockIdx.x * (unsigned)blockDim.x + threadIdx.x) >> 5);
    int lane = threadIdx.x & 31;
    if (w >= ET) return;
    int src = g_src[w];
    int dst = g_dst[w];

    int h = lane >> 3;
    float wv = g_w[(size_t)w * HEADS + h];
    float dn = g_denom[(size_t)dst * HEADS + h];
    float a = wv / (dn + 1e-16f);

    float4 xl4 = *(const float4*)(&g_xlxr[(size_t)src * 256 + 4 * lane]);
    float* p = out + (size_t)dst * HID + 4 * lane;
    asm volatile("red.global.add.v4.f32 [%0], {%1,%2,%3,%4};"
                 :: "l"(p), "f"(xl4.x * a), "f"(xl4.y * a), "f"(xl4.z * a), "f"(xl4.w * a)
                 : "memory");
}

// ---------------- init / relu / pool / head ----------------
__global__ void init_layer(float* __restrict__ out, const float* __restrict__ bias, int N)
{
    int i = blockIdx.x * blockDim.x + threadIdx.x;
    if (i < N * HID) out[i] = bias[i & (HID - 1)];
    if (i < N * HEADS) g_denom[i] = 0.f;
}

__global__ void relu_kernel(float* __restrict__ v, int n)
{
    int i = blockIdx.x * blockDim.x + threadIdx.x;
    if (i < n) v[i] = fmaxf(v[i], 0.f);
}

__global__ void init_pool()
{
    int i = blockIdx.x * blockDim.x + threadIdx.x;
    if (i < NGRAPH * HID) g_pool[i] = 0.f;
    if (i < NGRAPH) g_cnt[i] = 0.f;
}

__global__ void pool_kernel(const float* __restrict__ h, int N)
{
    int j = threadIdx.x;                // 128
    int n0 = blockIdx.x * 128;
    if (n0 >= N) return;
    int nend = min(n0 + 128, N);
    int cur = g_batch[n0];
    float acc = 0.f, c = 0.f;
    for (int n = n0; n < nend; n++) {
        int g = g_batch[n];
        if (g != cur) {
            atomicAdd(&g_pool[cur * HID + j], acc);
            if (j == 0) atomicAdd(&g_cnt[cur], c);
            acc = 0.f; c = 0.f; cur = g;
        }
        acc += h[(size_t)n * HID + j];
        c += 1.f;
    }
    atomicAdd(&g_pool[cur * HID + j], acc);
    if (j == 0) atomicAdd(&g_cnt[cur], c);
}

__global__ void head_kernel(const float* __restrict__ Wlin, const float* __restrict__ blin,
                            float* __restrict__ out)
{
    int g = threadIdx.x;
    if (g >= NGRAPH) return;
    float cnt = fmaxf(g_cnt[g], 1.f);
    float s = 0.f;
#pragma unroll 4
    for (int k = 0; k < HID; k++) s += g_pool[g * HID + k] * Wlin[k];
    out[g] = s / cnt + blin[0];
}

// ---------------- launch ----------------
extern "C" void kernel_launch(void* const* d_in, const int* in_sizes, int n_in,
                              void* d_out, int out_size)
{
    const float* x     = (const float*)d_in[0];
    const void*  ei    = d_in[1];
    const void*  batch = d_in[2];
    const float* Wl1  = (const float*)d_in[3];
    const float* bl1  = (const float*)d_in[4];
    const float* Wr1  = (const float*)d_in[5];
    const float* br1  = (const float*)d_in[6];
    const float* att1 = (const float*)d_in[7];
    const float* bias1= (const float*)d_in[8];
    const float* Wl2  = (const float*)d_in[9];
    const float* bl2  = (const float*)d_in[10];
    const float* Wr2  = (const float*)d_in[11];
    const float* br2  = (const float*)d_in[12];
    const float* att2 = (const float*)d_in[13];
    const float* bias2= (const float*)d_in[14];
    const float* Wlin = (const float*)d_in[15];
    const float* blin = (const float*)d_in[16];

    int hidden = in_sizes[4];              // 128
    int Fin    = in_sizes[3] / hidden;     // 256
    int N      = in_sizes[0] / Fin;        // 50000
    int E      = in_sizes[1] / 2;          // 1600000
    int ET     = E + N;

    float *xlxr, *h1, *h2;
    cudaGetSymbolAddress((void**)&xlxr, g_xlxr);
    cudaGetSymbolAddress((void**)&h1, g_h1);
    cudaGetSymbolAddress((void**)&h2, g_h2);

    int nhid = N * HID;
    int initBlocks = (nhid + 255) / 256;
    int edgeBlocks = (int)(((long long)ET * 32 + 255) / 256);
    dim3 gemmGrid((N + 127) / 128, 2);

    detect_kernel<<<1, 32>>>((const unsigned*)ei);
    convert_kernel<<<2048, 256>>>(ei, batch, E, N);

    // ---- layer 1 ----
    init_layer<<<initBlocks, 256>>>(h1, bias1, N);
    gemm_nt<<<gemmGrid, 256>>>(x, Wl1, Wr1, bl1, br1, xlxr, N, Fin);
    edge_alpha<<<edgeBlocks, 256>>>(ET, att1);
    edge_agg<<<edgeBlocks, 256>>>(ET, h1);
    relu_kernel<<<initBlocks, 256>>>(h1, nhid);

    // ---- layer 2 ----
    init_layer<<<initBlocks, 256>>>(h2, bias2, N);
    gemm_nt<<<gemmGrid, 256>>>(h1, Wl2, Wr2, bl2, br2, xlxr, N, hidden);
    edge_alpha<<<edgeBlocks, 256>>>(ET, att2);
    edge_agg<<<edgeBlocks, 256>>>(ET, h2);

    // ---- pool + head ----
    init_pool<<<(NGRAPH * HID + 255) / 256, 256>>>();
    pool_kernel<<<(N + 127) / 128, 128>>>(h2, N);
    head_kernel<<<1, 64>>>(Wlin, blin, (float*)d_out);
}

// round 4
// speedup vs baseline: 1.9042x; 1.9042x over previous
#include <cuda_runtime.h>

// ---------------- problem constants ----------------
#define MAXN 50000
#define MAXE 1600000
#define HID 128
#define HEADS 4
#define NGRAPH 64

// ---------------- scratch (static device memory; no allocations) ----------------
__device__ __align__(256) float g_xlxr[(size_t)MAXN * 256]; // [N,256]: 0..127 = xl, 128..255 = xr
__device__ __align__(256) float g_h1[(size_t)MAXN * HID];
__device__ __align__(256) float g_h2[(size_t)MAXN * HID];
__device__ __align__(256) int   g_src[MAXE + MAXN];
__device__ __align__(256) int   g_dst[MAXE + MAXN];
__device__ __align__(256) int   g_csr[MAXE + MAXN];     // src ids grouped by dst
__device__ __align__(256) int   g_deg[MAXN];
__device__ __align__(256) int   g_rowstart[MAXN + 1];
__device__ __align__(256) int   g_cursor[MAXN];
__device__ __align__(256) int   g_batch[MAXN];
__device__ float g_pool[NGRAPH * HID];
__device__ float g_cnt[NGRAPH];
__device__ int   g_is64;

// ---------------- dtype detect: int64 indices have zero high words ----------------
__global__ void detect_kernel(const unsigned* __restrict__ p)
{
    if (threadIdx.x == 0) {
        unsigned o = 0;
        for (int i = 0; i < 256; i++) o |= p[2 * i + 1];
        g_is64 = (o == 0) ? 1 : 0;
    }
}

__device__ __forceinline__ int load_idx(const void* p, int i, int is64, int N)
{
    long long v = is64 ? ((const long long*)p)[i] : (long long)((const int*)p)[i];
    int r = (int)v;
    return r < 0 ? 0 : (r >= N ? N - 1 : r);
}

__global__ void zero_deg(int N)
{
    int i = blockIdx.x * blockDim.x + threadIdx.x;
    if (i < N) g_deg[i] = 0;
}

// canonicalize edges (+self loops) + batch to int32, fused degree histogram
__global__ void convert_kernel(const void* __restrict__ ei, const void* __restrict__ batch,
                               int E, int N)
{
    int is64 = g_is64;
    int ET = E + N;
    for (int i = blockIdx.x * blockDim.x + threadIdx.x; i < ET;
         i += gridDim.x * blockDim.x) {
        int s, d;
        if (i < E) {
            s = load_idx(ei, i, is64, N);
            d = load_idx(ei, E + i, is64, N);
        } else {
            s = d = i - E;
        }
        g_src[i] = s;
        g_dst[i] = d;
        atomicAdd(&g_deg[d], 1);
        if (i < N) g_batch[i] = load_idx(batch, i, is64, NGRAPH);
    }
}

// single-block exclusive scan of degrees -> rowstart, cursor
__global__ void scan_kernel(int N)
{
    __shared__ int sdata[1024];
    __shared__ int s_carry;
    int t = threadIdx.x;
    if (t == 0) s_carry = 0;
    __syncthreads();
    for (int base = 0; base < N; base += 1024) {
        int carry = s_carry;
        int i = base + t;
        int v = (i < N) ? g_deg[i] : 0;
        sdata[t] = v;
        __syncthreads();
        for (int off = 1; off < 1024; off <<= 1) {
            int add = (t >= off) ? sdata[t - off] : 0;
            __syncthreads();
            sdata[t] += add;
            __syncthreads();
        }
        int excl = carry + sdata[t] - v;
        if (i < N) { g_rowstart[i] = excl; g_cursor[i] = excl; }
        __syncthreads();
        if (t == 1023) s_carry = carry + sdata[1023];
        __syncthreads();
    }
    if (t == 0) g_rowstart[N] = s_carry;
}

__global__ void scatter_kernel(int ET)
{
    for (int i = blockIdx.x * blockDim.x + threadIdx.x; i < ET;
         i += gridDim.x * blockDim.x) {
        int d = g_dst[i];
        int pos = atomicAdd(&g_cursor[d], 1);
        g_csr[pos] = g_src[i];
    }
}

// ---------------- fused GEMM: C[:,0:128] = A @ Wl^T + bl ; C[:,128:256] = A @ Wr^T + br ----
__global__ void gemm_nt(const float* __restrict__ A,
                        const float* __restrict__ Wl, const float* __restrict__ Wr,
                        const float* __restrict__ bl, const float* __restrict__ br,
                        float* __restrict__ C, int M, int K)
{
    __shared__ float As[8][128];
    __shared__ float Ws[8][128];
    const float* W  = blockIdx.y ? Wr : Wl;
    const float* bv = blockIdx.y ? br : bl;

    int m0 = blockIdx.x * 128;
    int t = threadIdx.x;               // 256 threads
    int tx = t & 15;
    int ty = t >> 4;
    int lrow = t >> 1;                 // 0..127
    int lseg = (t & 1) * 4;            // 0 or 4

    float acc[8][8];
#pragma unroll
    for (int i = 0; i < 8; i++)
#pragma unroll
        for (int j = 0; j < 8; j++) acc[i][j] = 0.f;

    for (int k0 = 0; k0 < K; k0 += 8) {
        int ar = m0 + lrow;
        int arc = ar < M ? ar : M - 1;
        float4 av = *(const float4*)(A + (size_t)arc * K + k0 + lseg);
        As[lseg + 0][lrow] = av.x; As[lseg + 1][lrow] = av.y;
        As[lseg + 2][lrow] = av.z; As[lseg + 3][lrow] = av.w;
        float4 wv = *(const float4*)(W + (size_t)lrow * K + k0 + lseg);
        Ws[lseg + 0][lrow] = wv.x; Ws[lseg + 1][lrow] = wv.y;
        Ws[lseg + 2][lrow] = wv.z; Ws[lseg + 3][lrow] = wv.w;
        __syncthreads();
#pragma unroll
        for (int kk = 0; kk < 8; kk++) {
            float4 a0 = *(const float4*)&As[kk][ty * 8];
            float4 a1 = *(const float4*)&As[kk][ty * 8 + 4];
            float4 w0 = *(const float4*)&Ws[kk][tx * 8];
            float4 w1 = *(const float4*)&Ws[kk][tx * 8 + 4];
            float ra[8] = {a0.x, a0.y, a0.z, a0.w, a1.x, a1.y, a1.z, a1.w};
            float rw[8] = {w0.x, w0.y, w0.z, w0.w, w1.x, w1.y, w1.z, w1.w};
#pragma unroll
            for (int i = 0; i < 8; i++)
#pragma unroll
                for (int j = 0; j < 8; j++) acc[i][j] += ra[i] * rw[j];
        }
        __syncthreads();
    }

    float bias[8];
#pragma unroll
    for (int j = 0; j < 8; j++) bias[j] = bv[tx * 8 + j];

#pragma unroll
    for (int i = 0; i < 8; i++) {
        int row = m0 + ty * 8 + i;
        if (row < M) {
            float* dst = C + (size_t)row * 256 + blockIdx.y * 128 + tx * 8;
            *(float4*)(dst + 0) = make_float4(acc[i][0] + bias[0], acc[i][1] + bias[1],
                                              acc[i][2] + bias[2], acc[i][3] + bias[3]);
            *(float4*)(dst + 4) = make_float4(acc[i][4] + bias[4], acc[i][5] + bias[5],
                                              acc[i][6] + bias[6], acc[i][7] + bias[7]);
        }
    }
}

// ---------------- fused node kernel: attention + softmax + aggregate + bias (+relu) ----
// one warp per dst node. lane owns channels 4l..4l+3 (head = lane>>3).
__device__ __forceinline__ float lrelu(float x) {
    return fmaxf(x, 0.f) + 0.2f * fminf(x, 0.f);
}

__global__ void node_gather(const float* __restrict__ att, const float* __restrict__ bias,
                            float* __restrict__ out, int N, int dorelu)
{
    int v = (int)((blockIdx.x * (unsigned)blockDim.x + threadIdx.x) >> 5);
    int lane = threadIdx.x & 31;
    if (v >= N) return;

    float4 a4  = ((const float4*)att)[lane];
    float4 xr4 = *(const float4*)&g_xlxr[(size_t)v * 256 + 128 + 4 * lane];

    int beg = g_rowstart[v];
    int end = g_rowstart[v + 1];

    float4 acc = make_float4(0.f, 0.f, 0.f, 0.f);
    float den = 0.f;

    int   s_next = 0;
    float4 xl_next = make_float4(0.f, 0.f, 0.f, 0.f);
    if (beg < end) {
        s_next = g_csr[beg];
        xl_next = *(const float4*)&g_xlxr[(size_t)s_next * 256 + 4 * lane];
    }

    for (int e = beg; e < end; e++) {
        float4 xl = xl_next;
        if (e + 1 < end) {
            int sn = g_csr[e + 1];
            xl_next = *(const float4*)&g_xlxr[(size_t)sn * 256 + 4 * lane];
        }
        float p = lrelu(xl.x + xr4.x) * a4.x
                + lrelu(xl.y + xr4.y) * a4.y
                + lrelu(xl.z + xr4.z) * a4.z
                + lrelu(xl.w + xr4.w) * a4.w;
        p += __shfl_xor_sync(0xFFFFFFFFu, p, 1);
        p += __shfl_xor_sync(0xFFFFFFFFu, p, 2);
        p += __shfl_xor_sync(0xFFFFFFFFu, p, 4);
        float w = __expf(p);
        acc.x += w * xl.x;
        acc.y += w * xl.y;
        acc.z += w * xl.z;
        acc.w += w * xl.w;
        den += w;
    }

    float inv = 1.f / (den + 1e-16f);
    const float4 b4 = ((const float4*)bias)[lane];
    float4 o = make_float4(acc.x * inv + b4.x, acc.y * inv + b4.y,
                           acc.z * inv + b4.z, acc.w * inv + b4.w);
    if (dorelu) {
        o.x = fmaxf(o.x, 0.f); o.y = fmaxf(o.y, 0.f);
        o.z = fmaxf(o.z, 0.f); o.w = fmaxf(o.w, 0.f);
    }
    *(float4*)&out[(size_t)v * HID + 4 * lane] = o;
}

// ---------------- pool / head ----------------
__global__ void init_pool()
{
    int i = blockIdx.x * blockDim.x + threadIdx.x;
    if (i < NGRAPH * HID) g_pool[i] = 0.f;
    if (i < NGRAPH) g_cnt[i] = 0.f;
}

__global__ void pool_kernel(const float* __restrict__ h, int N)
{
    int j = threadIdx.x;                // 128
    int n0 = blockIdx.x * 128;
    if (n0 >= N) return;
    int nend = min(n0 + 128, N);
    int cur = g_batch[n0];
    float acc = 0.f, c = 0.f;
    for (int n = n0; n < nend; n++) {
        int g = g_batch[n];
        if (g != cur) {
            atomicAdd(&g_pool[cur * HID + j], acc);
            if (j == 0) atomicAdd(&g_cnt[cur], c);
            acc = 0.f; c = 0.f; cur = g;
        }
        acc += h[(size_t)n * HID + j];
        c += 1.f;
    }
    atomicAdd(&g_pool[cur * HID + j], acc);
    if (j == 0) atomicAdd(&g_cnt[cur], c);
}

__global__ void head_kernel(const float* __restrict__ Wlin, const float* __restrict__ blin,
                            float* __restrict__ out)
{
    int g = threadIdx.x;
    if (g >= NGRAPH) return;
    float cnt = fmaxf(g_cnt[g], 1.f);
    float s = 0.f;
#pragma unroll 4
    for (int k = 0; k < HID; k++) s += g_pool[g * HID + k] * Wlin[k];
    out[g] = s / cnt + blin[0];
}

// ---------------- launch ----------------
extern "C" void kernel_launch(void* const* d_in, const int* in_sizes, int n_in,
                              void* d_out, int out_size)
{
    const float* x     = (const float*)d_in[0];
    const void*  ei    = d_in[1];
    const void*  batch = d_in[2];
    const float* Wl1  = (const float*)d_in[3];
    const float* bl1  = (const float*)d_in[4];
    const float* Wr1  = (const float*)d_in[5];
    const float* br1  = (const float*)d_in[6];
    const float* att1 = (const float*)d_in[7];
    const float* bias1= (const float*)d_in[8];
    const float* Wl2  = (const float*)d_in[9];
    const float* bl2  = (const float*)d_in[10];
    const float* Wr2  = (const float*)d_in[11];
    const float* br2  = (const float*)d_in[12];
    const float* att2 = (const float*)d_in[13];
    const float* bias2= (const float*)d_in[14];
    const float* Wlin = (const float*)d_in[15];
    const float* blin = (const float*)d_in[16];

    int hidden = in_sizes[4];              // 128
    int Fin    = in_sizes[3] / hidden;     // 256
    int N      = in_sizes[0] / Fin;        // 50000
    int E      = in_sizes[1] / 2;          // 1600000
    int ET     = E + N;

    float *xlxr, *h1, *h2;
    cudaGetSymbolAddress((void**)&xlxr, g_xlxr);
    cudaGetSymbolAddress((void**)&h1, g_h1);
    cudaGetSymbolAddress((void**)&h2, g_h2);

    int nodeBlocks = (int)(((long long)N * 32 + 255) / 256);
    dim3 gemmGrid((N + 127) / 128, 2);

    // ---- index canonicalization + CSR build (reused by both layers) ----
    detect_kernel<<<1, 32>>>((const unsigned*)ei);
    zero_deg<<<(N + 255) / 256, 256>>>(N);
    convert_kernel<<<2048, 256>>>(ei, batch, E, N);
    scan_kernel<<<1, 1024>>>(N);
    scatter_kernel<<<2048, 256>>>(ET);

    // ---- layer 1 ----
    gemm_nt<<<gemmGrid, 256>>>(x, Wl1, Wr1, bl1, br1, xlxr, N, Fin);
    node_gather<<<nodeBlocks, 256>>>(att1, bias1, h1, N, 1);

    // ---- layer 2 ----
    gemm_nt<<<gemmGrid, 256>>>(h1, Wl2, Wr2, bl2, br2, xlxr, N, hidden);
    node_gather<<<nodeBlocks, 256>>>(att2, bias2, h2, N, 0);

    // ---- pool + head ----
    init_pool<<<(NGRAPH * HID + 255) / 256, 256>>>();
    pool_kernel<<<(N + 127) / 128, 128>>>(h2, N);
    head_kernel<<<1, 64>>>(Wlin, blin, (float*)d_out);
}

// round 5
// speedup vs baseline: 2.2118x; 1.1615x over previous
#include <cuda_runtime.h>

// ---------------- problem constants ----------------
#define MAXN 50000
#define MAXE 1600000
#define HID 128
#define HEADS 4
#define NGRAPH 64
#define SCAN_B 1024

// ---------------- scratch (static device memory; no allocations) ----------------
__device__ __align__(256) float g_xlxr[(size_t)MAXN * 256]; // [N,256]: 0..127 = xl, 128..255 = xr
__device__ __align__(256) float g_h1[(size_t)MAXN * HID];
__device__ __align__(256) float g_h2[(size_t)MAXN * HID];
__device__ __align__(256) int   g_src[MAXE + MAXN];
__device__ __align__(256) int   g_dst[MAXE + MAXN];
__device__ __align__(256) int   g_csr[MAXE + MAXN];     // src ids grouped by dst
__device__ __align__(256) int   g_deg[MAXN];
__device__ __align__(256) int   g_rowstart[MAXN + 1];
__device__ __align__(256) int   g_cursor[MAXN];
__device__ __align__(256) int   g_batch[MAXN];
__device__ int   g_bsum[(MAXN + SCAN_B - 1) / SCAN_B];
__device__ int   g_total;
__device__ float g_pool[NGRAPH * HID];
__device__ float g_cnt[NGRAPH];
__device__ int   g_is64;

// ---------------- dtype detect: int64 indices have zero high words ----------------
__global__ void detect_kernel(const unsigned* __restrict__ p)
{
    if (threadIdx.x == 0) {
        unsigned o = 0;
        for (int i = 0; i < 256; i++) o |= p[2 * i + 1];
        g_is64 = (o == 0) ? 1 : 0;
    }
}

__device__ __forceinline__ int load_idx(const void* p, int i, int is64, int N)
{
    long long v = is64 ? ((const long long*)p)[i] : (long long)((const int*)p)[i];
    int r = (int)v;
    return r < 0 ? 0 : (r >= N ? N - 1 : r);
}

__global__ void zero_deg(int N)
{
    int i = blockIdx.x * blockDim.x + threadIdx.x;
    if (i < N) g_deg[i] = 0;
}

// canonicalize edges (+self loops) + batch to int32, fused degree histogram
__global__ void convert_kernel(const void* __restrict__ ei, const void* __restrict__ batch,
                               int E, int N)
{
    int is64 = g_is64;
    int ET = E + N;
    for (int i = blockIdx.x * blockDim.x + threadIdx.x; i < ET;
         i += gridDim.x * blockDim.x) {
        int s, d;
        if (i < E) {
            s = load_idx(ei, i, is64, N);
            d = load_idx(ei, E + i, is64, N);
        } else {
            s = d = i - E;
        }
        g_src[i] = s;
        g_dst[i] = d;
        atomicAdd(&g_deg[d], 1);
        if (i < N) g_batch[i] = load_idx(batch, i, is64, NGRAPH);
    }
}

// ---------------- hierarchical scan: block scans -> partial scan -> add ----------------
__global__ void scan_block(int N)
{
    int t = threadIdx.x;
    int i = blockIdx.x * SCAN_B + t;
    int v = (i < N) ? g_deg[i] : 0;
    int x = v;
#pragma unroll
    for (int o = 1; o < 32; o <<= 1) {
        int y = __shfl_up_sync(0xFFFFFFFFu, x, o);
        if ((t & 31) >= o) x += y;
    }
    __shared__ int wsum[32];
    if ((t & 31) == 31) wsum[t >> 5] = x;
    __syncthreads();
    if (t < 32) {
        int s = wsum[t];
#pragma unroll
        for (int o = 1; o < 32; o <<= 1) {
            int y = __shfl_up_sync(0xFFFFFFFFu, s, o);
            if (t >= o) s += y;
        }
        wsum[t] = s;
    }
    __syncthreads();
    int base = (t >= 32) ? wsum[(t >> 5) - 1] : 0;
    int incl = x + base;
    if (i < N) g_rowstart[i] = incl - v;            // exclusive, pre-block-offset
    if (t == SCAN_B - 1) g_bsum[blockIdx.x] = incl; // block total
}

__global__ void scan_partials(int nb)
{
    if (threadIdx.x == 0) {
        int s = 0;
        for (int b = 0; b < nb; b++) { int v = g_bsum[b]; g_bsum[b] = s; s += v; }
        g_total = s;
    }
}

__global__ void scan_add(int N)
{
    int i = blockIdx.x * blockDim.x + threadIdx.x;
    if (i < N) {
        int r = g_rowstart[i] + g_bsum[i >> 10];
        g_rowstart[i] = r;
        g_cursor[i] = r;
    }
    if (i == 0) g_rowstart[N] = g_total;
}

__global__ void scatter_kernel(int ET)
{
    for (int i = blockIdx.x * blockDim.x + threadIdx.x; i < ET;
         i += gridDim.x * blockDim.x) {
        int d = g_dst[i];
        int pos = atomicAdd(&g_cursor[d], 1);
        g_csr[pos] = g_src[i];
    }
}

// ---------------- fused GEMM (register-prefetch pipelined, BK=16) ----------------
// C[:,0:128] = A @ Wl^T + bl ; C[:,128:256] = A @ Wr^T + br  (blockIdx.y selects)
__global__ __launch_bounds__(256, 2)
void gemm_nt(const float* __restrict__ A,
             const float* __restrict__ Wl, const float* __restrict__ Wr,
             const float* __restrict__ bl, const float* __restrict__ br,
             float* __restrict__ C, int M, int K)
{
    __shared__ float As[16][128];
    __shared__ float Ws[16][128];
    const float* W  = blockIdx.y ? Wr : Wl;
    const float* bv = blockIdx.y ? br : bl;

    int m0 = blockIdx.x * 128;
    int t = threadIdx.x;               // 256 threads
    int tx = t & 15;
    int ty = t >> 4;
    int lrow = t >> 1;                 // 0..127
    int lseg = (t & 1) * 8;            // 0 or 8

    float acc[8][8];
#pragma unroll
    for (int i = 0; i < 8; i++)
#pragma unroll
        for (int j = 0; j < 8; j++) acc[i][j] = 0.f;

    int ar = m0 + lrow;
    int arc = ar < M ? ar : M - 1;
    const float* Arow = A + (size_t)arc * K;
    const float* Wrow = W + (size_t)lrow * K;

    // prefetch tile 0
    float4 a0 = *(const float4*)(Arow + lseg);
    float4 a1 = *(const float4*)(Arow + lseg + 4);
    float4 w0 = *(const float4*)(Wrow + lseg);
    float4 w1 = *(const float4*)(Wrow + lseg + 4);

    for (int k0 = 0; k0 < K; k0 += 16) {
        As[lseg + 0][lrow] = a0.x; As[lseg + 1][lrow] = a0.y;
        As[lseg + 2][lrow] = a0.z; As[lseg + 3][lrow] = a0.w;
        As[lseg + 4][lrow] = a1.x; As[lseg + 5][lrow] = a1.y;
        As[lseg + 6][lrow] = a1.z; As[lseg + 7][lrow] = a1.w;
        Ws[lseg + 0][lrow] = w0.x; Ws[lseg + 1][lrow] = w0.y;
        Ws[lseg + 2][lrow] = w0.z; Ws[lseg + 3][lrow] = w0.w;
        Ws[lseg + 4][lrow] = w1.x; Ws[lseg + 5][lrow] = w1.y;
        Ws[lseg + 6][lrow] = w1.z; Ws[lseg + 7][lrow] = w1.w;
        __syncthreads();

        if (k0 + 16 < K) {  // prefetch next tile (hidden under compute)
            a0 = *(const float4*)(Arow + k0 + 16 + lseg);
            a1 = *(const float4*)(Arow + k0 + 16 + lseg + 4);
            w0 = *(const float4*)(Wrow + k0 + 16 + lseg);
            w1 = *(const float4*)(Wrow + k0 + 16 + lseg + 4);
        }

#pragma unroll
        for (int kk = 0; kk < 16; kk++) {
            float4 ra0 = *(const float4*)&As[kk][ty * 8];
            float4 ra1 = *(const float4*)&As[kk][ty * 8 + 4];
            float4 rw0 = *(const float4*)&Ws[kk][tx * 8];
            float4 rw1 = *(const float4*)&Ws[kk][tx * 8 + 4];
            float ra[8] = {ra0.x, ra0.y, ra0.z, ra0.w, ra1.x, ra1.y, ra1.z, ra1.w};
            float rw[8] = {rw0.x, rw0.y, rw0.z, rw0.w, rw1.x, rw1.y, rw1.z, rw1.w};
#pragma unroll
            for (int i = 0; i < 8; i++)
#pragma unroll
                for (int j = 0; j < 8; j++) acc[i][j] += ra[i] * rw[j];
        }
        __syncthreads();
    }

    float bias[8];
#pragma unroll
    for (int j = 0; j < 8; j++) bias[j] = bv[tx * 8 + j];

#pragma unroll
    for (int i = 0; i < 8; i++) {
        int row = m0 + ty * 8 + i;
        if (row < M) {
            float* dst = C + (size_t)row * 256 + blockIdx.y * 128 + tx * 8;
            *(float4*)(dst + 0) = make_float4(acc[i][0] + bias[0], acc[i][1] + bias[1],
                                              acc[i][2] + bias[2], acc[i][3] + bias[3]);
            *(float4*)(dst + 4) = make_float4(acc[i][4] + bias[4], acc[i][5] + bias[5],
                                              acc[i][6] + bias[6], acc[i][7] + bias[7]);
        }
    }
}

// ---------------- fused node kernel: attention + softmax + aggregate + bias (+relu) ----
__device__ __forceinline__ float lrelu(float x) {
    return fmaxf(x, 0.f) + 0.2f * fminf(x, 0.f);
}

__global__ void node_gather(const float* __restrict__ att, const float* __restrict__ bias,
                            float* __restrict__ out, int N, int dorelu)
{
    int v = (int)((blockIdx.x * (unsigned)blockDim.x + threadIdx.x) >> 5);
    int lane = threadIdx.x & 31;
    if (v >= N) return;

    float4 a4  = ((const float4*)att)[lane];
    float4 xr4 = *(const float4*)&g_xlxr[(size_t)v * 256 + 128 + 4 * lane];

    int beg = g_rowstart[v];
    int end = g_rowstart[v + 1];

    float4 acc = make_float4(0.f, 0.f, 0.f, 0.f);
    float den = 0.f;

    float4 xl_next = make_float4(0.f, 0.f, 0.f, 0.f);
    if (beg < end) {
        int s0 = g_csr[beg];
        xl_next = *(const float4*)&g_xlxr[(size_t)s0 * 256 + 4 * lane];
    }

    for (int e = beg; e < end; e++) {
        float4 xl = xl_next;
        if (e + 1 < end) {
            int sn = g_csr[e + 1];
            xl_next = *(const float4*)&g_xlxr[(size_t)sn * 256 + 4 * lane];
        }
        float p = lrelu(xl.x + xr4.x) * a4.x
                + lrelu(xl.y + xr4.y) * a4.y
                + lrelu(xl.z + xr4.z) * a4.z
                + lrelu(xl.w + xr4.w) * a4.w;
        p += __shfl_xor_sync(0xFFFFFFFFu, p, 1);
        p += __shfl_xor_sync(0xFFFFFFFFu, p, 2);
        p += __shfl_xor_sync(0xFFFFFFFFu, p, 4);
        float w = __expf(p);
        acc.x += w * xl.x;
        acc.y += w * xl.y;
        acc.z += w * xl.z;
        acc.w += w * xl.w;
        den += w;
    }

    float inv = 1.f / (den + 1e-16f);
    const float4 b4 = ((const float4*)bias)[lane];
    float4 o = make_float4(acc.x * inv + b4.x, acc.y * inv + b4.y,
                           acc.z * inv + b4.z, acc.w * inv + b4.w);
    if (dorelu) {
        o.x = fmaxf(o.x, 0.f); o.y = fmaxf(o.y, 0.f);
        o.z = fmaxf(o.z, 0.f); o.w = fmaxf(o.w, 0.f);
    }
    *(float4*)&out[(size_t)v * HID + 4 * lane] = o;
}

// ---------------- pool / head ----------------
__global__ void init_pool()
{
    int i = blockIdx.x * blockDim.x + threadIdx.x;
    if (i < NGRAPH * HID) g_pool[i] = 0.f;
    if (i < NGRAPH) g_cnt[i] = 0.f;
}

__global__ void pool_kernel(const float* __restrict__ h, int N)
{
    int j = threadIdx.x;                // 128
    int n0 = blockIdx.x * 128;
    if (n0 >= N) return;
    int nend = min(n0 + 128, N);
    int cur = g_batch[n0];
    float acc = 0.f, c = 0.f;
    for (int n = n0; n < nend; n++) {
        int g = g_batch[n];
        if (g != cur) {
            atomicAdd(&g_pool[cur * HID + j], acc);
            if (j == 0) atomicAdd(&g_cnt[cur], c);
            acc = 0.f; c = 0.f; cur = g;
        }
        acc += h[(size_t)n * HID + j];
        c += 1.f;
    }
    atomicAdd(&g_pool[cur * HID + j], acc);
    if (j == 0) atomicAdd(&g_cnt[cur], c);
}

__global__ void head_kernel(const float* __restrict__ Wlin, const float* __restrict__ blin,
                            float* __restrict__ out)
{
    int g = threadIdx.x;
    if (g >= NGRAPH) return;
    float cnt = fmaxf(g_cnt[g], 1.f);
    float s = 0.f;
#pragma unroll 4
    for (int k = 0; k < HID; k++) s += g_pool[g * HID + k] * Wlin[k];
    out[g] = s / cnt + blin[0];
}

// ---------------- launch ----------------
extern "C" void kernel_launch(void* const* d_in, const int* in_sizes, int n_in,
                              void* d_out, int out_size)
{
    const float* x     = (const float*)d_in[0];
    const void*  ei    = d_in[1];
    const void*  batch = d_in[2];
    const float* Wl1  = (const float*)d_in[3];
    const float* bl1  = (const float*)d_in[4];
    const float* Wr1  = (const float*)d_in[5];
    const float* br1  = (const float*)d_in[6];
    const float* att1 = (const float*)d_in[7];
    const float* bias1= (const float*)d_in[8];
    const float* Wl2  = (const float*)d_in[9];
    const float* bl2  = (const float*)d_in[10];
    const float* Wr2  = (const float*)d_in[11];
    const float* br2  = (const float*)d_in[12];
    const float* att2 = (const float*)d_in[13];
    const float* bias2= (const float*)d_in[14];
    const float* Wlin = (const float*)d_in[15];
    const float* blin = (const float*)d_in[16];

    int hidden = in_sizes[4];              // 128
    int Fin    = in_sizes[3] / hidden;     // 256
    int N      = in_sizes[0] / Fin;        // 50000
    int E      = in_sizes[1] / 2;          // 1600000
    int ET     = E + N;
    int nb     = (N + SCAN_B - 1) / SCAN_B;

    float *xlxr, *h1, *h2;
    cudaGetSymbolAddress((void**)&xlxr, g_xlxr);
    cudaGetSymbolAddress((void**)&h1, g_h1);
    cudaGetSymbolAddress((void**)&h2, g_h2);

    int nodeBlocks = (int)(((long long)N * 32 + 255) / 256);
    dim3 gemmGrid((N + 127) / 128, 2);

    // ---- index canonicalization + CSR build (reused by both layers) ----
    detect_kernel<<<1, 32>>>((const unsigned*)ei);
    zero_deg<<<(N + 255) / 256, 256>>>(N);
    convert_kernel<<<2048, 256>>>(ei, batch, E, N);
    scan_block<<<nb, SCAN_B>>>(N);
    scan_partials<<<1, 32>>>(nb);
    scan_add<<<(N + 255) / 256, 256>>>(N);
    scatter_kernel<<<2048, 256>>>(ET);

    // ---- layer 1 ----
    gemm_nt<<<gemmGrid, 256>>>(x, Wl1, Wr1, bl1, br1, xlxr, N, Fin);
    node_gather<<<nodeBlocks, 256>>>(att1, bias1, h1, N, 1);

    // ---- layer 2 ----
    gemm_nt<<<gemmGrid, 256>>>(h1, Wl2, Wr2, bl2, br2, xlxr, N, hidden);
    node_gather<<<nodeBlocks, 256>>>(att2, bias2, h2, N, 0);

    // ---- pool + head ----
    init_pool<<<(NGRAPH * HID + 255) / 256, 256>>>();
    pool_kernel<<<(N + 127) / 128, 128>>>(h2, N);
    head_kernel<<<1, 64>>>(Wlin, blin, (float*)d_out);
}